// round 1
// baseline (speedup 1.0000x reference)
#include <cuda_runtime.h>
#include <cstdint>

#define NUM_EXPERTS 16
#define BATCH       1024
#define IDIM        512
#define UNITS       512

#define BM 64
#define BN 64
#define BK 32
#define THREADS 256

// scratch (device globals: allocation-free, harness-legal)
__device__ int g_order[BATCH];
__device__ int g_off[NUM_EXPERTS + 1];

// ---------------------------------------------------------------------------
// prep: counting sort of sample ids by expert. Handles both int64 and int32
// index dtype: if the buffer is int64 (LE), every odd 32-bit word of valid
// indices (0..15) is zero; if it's int32 data, odd words are real indices and
// the chance they're ALL zero is 16^-512.
// ---------------------------------------------------------------------------
__global__ void prep_kernel(const void* idx_raw)
{
    const int* i32 = (const int*)idx_raw;
    __shared__ int cnt[NUM_EXPERTS];
    __shared__ int off[NUM_EXPERTS];
    __shared__ int cur[NUM_EXPERTS];
    __shared__ int odd_nonzero;

    int t = threadIdx.x;
    if (t == 0) odd_nonzero = 0;
    if (t < NUM_EXPERTS) { cnt[t] = 0; cur[t] = 0; }
    __syncthreads();

    // probe only the first 4KB (safe under both dtypes)
    if (t < 512) {
        if (i32[2 * t + 1] != 0) atomicOr(&odd_nonzero, 1);
    }
    __syncthreads();

    int e;
    if (odd_nonzero) e = i32[t];          // int32 data
    else             e = i32[2 * t];      // int64 data, low word
    e &= (NUM_EXPERTS - 1);               // safety clamp

    atomicAdd(&cnt[e], 1);
    __syncthreads();

    if (t == 0) {
        int s = 0;
        for (int i = 0; i < NUM_EXPERTS; i++) {
            off[i] = s;
            g_off[i] = s;
            s += cnt[i];
        }
        g_off[NUM_EXPERTS] = s;
    }
    __syncthreads();

    int p = atomicAdd(&cur[e], 1);
    g_order[off[e] + p] = t;
}

// ---------------------------------------------------------------------------
// grouped GEMM: block = (unit tile n0, expert e). Computes
//   out[rows_of_e][n0:n0+64] = relu( X[rows_of_e] @ W[e][:, n0:n0+64] + b )
// BM=64 x BN=64 x BK=32 SMEM tiles, 4x4 register micro-tile per thread.
// ---------------------------------------------------------------------------
__global__ __launch_bounds__(THREADS)
void gemm_kernel(const float* __restrict__ x,
                 const float* __restrict__ ws,
                 const float* __restrict__ bs,
                 float* __restrict__ out)
{
    const int e  = blockIdx.y;
    const int n0 = blockIdx.x * BN;

    const int base = g_off[e];
    const int cnt  = g_off[e + 1] - base;
    if (cnt == 0) return;

    __shared__ float As[BK][BM + 4];   // transposed A tile: As[k][m], +4 pad keeps 16B align
    __shared__ float Bs[BK][BN];       // Bs[k][n]

    const int t  = threadIdx.x;
    const int tx = t & 15;             // n micro index
    const int ty = t >> 4;             // m micro index

    // A-load mapping: 8 threads per row, each loads one float4 (4 k-values), 2 passes
    const int a_row = t >> 3;          // 0..31
    const int a_k4  = (t & 7) * 4;     // 0,4,...,28

    // B-load mapping: each thread loads 2 float4s
    const int b_k0  = t >> 4;          // 0..15
    const int b_n0  = (t & 15) * 4;    // 0..60

    const float* wbase = ws + ((long long)e * IDIM) * UNITS + n0;

    for (int m0 = 0; m0 < cnt; m0 += BM) {

        float acc[4][4];
#pragma unroll
        for (int i = 0; i < 4; i++)
#pragma unroll
            for (int j = 0; j < 4; j++) acc[i][j] = 0.0f;

        // prefetch gathered global rows for this m-tile (2 per thread-pass)
        int gr0 = (m0 + a_row      < cnt) ? g_order[base + m0 + a_row]      : -1;
        int gr1 = (m0 + a_row + 32 < cnt) ? g_order[base + m0 + a_row + 32] : -1;

        for (int k0 = 0; k0 < IDIM; k0 += BK) {
            // ---- load A tile (gathered, transposed into As[k][m]) ----
            {
                float4 v0 = make_float4(0.f, 0.f, 0.f, 0.f);
                float4 v1 = make_float4(0.f, 0.f, 0.f, 0.f);
                if (gr0 >= 0) v0 = *(const float4*)&x[(long long)gr0 * IDIM + k0 + a_k4];
                if (gr1 >= 0) v1 = *(const float4*)&x[(long long)gr1 * IDIM + k0 + a_k4];
                As[a_k4 + 0][a_row]      = v0.x;
                As[a_k4 + 1][a_row]      = v0.y;
                As[a_k4 + 2][a_row]      = v0.z;
                As[a_k4 + 3][a_row]      = v0.w;
                As[a_k4 + 0][a_row + 32] = v1.x;
                As[a_k4 + 1][a_row + 32] = v1.y;
                As[a_k4 + 2][a_row + 32] = v1.z;
                As[a_k4 + 3][a_row + 32] = v1.w;
            }
            // ---- load B tile: ws[e][k0+k][n0..n0+63] ----
            {
                float4 w0 = *(const float4*)&wbase[(long long)(k0 + b_k0)      * UNITS + b_n0];
                float4 w1 = *(const float4*)&wbase[(long long)(k0 + b_k0 + 16) * UNITS + b_n0];
                *(float4*)&Bs[b_k0][b_n0]      = w0;
                *(float4*)&Bs[b_k0 + 16][b_n0] = w1;
            }
            __syncthreads();

            // ---- compute ----
#pragma unroll
            for (int k = 0; k < BK; k++) {
                float4 a = *(const float4*)&As[k][ty * 4];
                float4 b = *(const float4*)&Bs[k][tx * 4];
                acc[0][0] += a.x * b.x; acc[0][1] += a.x * b.y; acc[0][2] += a.x * b.z; acc[0][3] += a.x * b.w;
                acc[1][0] += a.y * b.x; acc[1][1] += a.y * b.y; acc[1][2] += a.y * b.z; acc[1][3] += a.y * b.w;
                acc[2][0] += a.z * b.x; acc[2][1] += a.z * b.y; acc[2][2] += a.z * b.z; acc[2][3] += a.z * b.w;
                acc[3][0] += a.w * b.x; acc[3][1] += a.w * b.y; acc[3][2] += a.w * b.z; acc[3][3] += a.w * b.w;
            }
            __syncthreads();
        }

        // ---- epilogue: bias + relu, scatter to gathered rows ----
        float4 bias = *(const float4*)&bs[e * UNITS + n0 + tx * 4];
#pragma unroll
        for (int i = 0; i < 4; i++) {
            int m = m0 + ty * 4 + i;
            if (m < cnt) {
                int gr = g_order[base + m];
                float4 r;
                r.x = fmaxf(acc[i][0] + bias.x, 0.0f);
                r.y = fmaxf(acc[i][1] + bias.y, 0.0f);
                r.z = fmaxf(acc[i][2] + bias.z, 0.0f);
                r.w = fmaxf(acc[i][3] + bias.w, 0.0f);
                *(float4*)&out[(long long)gr * UNITS + n0 + tx * 4] = r;
            }
        }
    }
}

extern "C" void kernel_launch(void* const* d_in, const int* in_sizes, int n_in,
                              void* d_out, int out_size)
{
    const float* x   = (const float*)d_in[0];
    const void*  idx = d_in[1];
    const float* ws  = (const float*)d_in[2];
    const float* bs  = (const float*)d_in[3];
    float* out = (float*)d_out;

    prep_kernel<<<1, BATCH>>>(idx);
    dim3 grid(UNITS / BN, NUM_EXPERTS);
    gemm_kernel<<<grid, THREADS>>>(x, ws, bs, out);
}

// round 2
// speedup vs baseline: 1.2037x; 1.2037x over previous
#include <cuda_runtime.h>
#include <cstdint>

#define NUM_EXPERTS 16
#define BATCH       1024
#define IDIM        512
#define UNITS       512

#define BM 64
#define BN 32
#define BK 16
#define THREADS 128
#define KTILES (IDIM / BK)          // 32
#define MAX_WORK 32                 // sum ceil(cnt/64) <= 31

// device-global scratch (allocation-free)
__device__ int g_order[BATCH];
__device__ int g_orderp[2048];      // padded order
__device__ int g_we[MAX_WORK];
__device__ int g_wstart[MAX_WORK];
__device__ int g_wvalid[MAX_WORK];
__device__ int g_nwork;

// ---------------------------------------------------------------------------
// prep: counting sort by expert, padded order array, and work list.
// Auto-detects int64 vs int32 index buffer (odd 32-bit words all zero => i64).
// ---------------------------------------------------------------------------
__global__ void prep_kernel(const void* idx_raw)
{
    const int* i32 = (const int*)idx_raw;
    __shared__ int cnt[NUM_EXPERTS];
    __shared__ int off[NUM_EXPERTS + 1];
    __shared__ int offp[NUM_EXPERTS + 1];
    __shared__ int cur[NUM_EXPERTS];
    __shared__ int odd_nonzero;

    int t = threadIdx.x;
    if (t == 0) odd_nonzero = 0;
    if (t < NUM_EXPERTS) { cnt[t] = 0; cur[t] = 0; }
    __syncthreads();

    if (t < 512) {
        if (i32[2 * t + 1] != 0) atomicOr(&odd_nonzero, 1);
    }
    __syncthreads();

    int e;
    if (odd_nonzero) e = i32[t];          // int32 data
    else             e = i32[2 * t];      // int64 data, low word
    e &= (NUM_EXPERTS - 1);

    atomicAdd(&cnt[e], 1);
    __syncthreads();

    if (t == 0) {
        int s = 0, sp = 0, nw = 0;
        for (int i = 0; i < NUM_EXPERTS; i++) {
            off[i] = s;
            offp[i] = sp;
            int c = cnt[i];
            int tiles = (c + BM - 1) / BM;
            for (int j = 0; j < tiles; j++) {
                g_we[nw] = i;
                g_wstart[nw] = sp + j * BM;
                int v = c - j * BM;
                g_wvalid[nw] = (v < BM) ? v : BM;
                nw++;
            }
            s += c;
            sp += tiles * BM;
        }
        off[NUM_EXPERTS] = s;
        offp[NUM_EXPERTS] = sp;
        g_nwork = nw;
    }
    __syncthreads();

    int p = atomicAdd(&cur[e], 1);
    g_order[off[e] + p] = t;
    __syncthreads();

    // fill padded order (pads duplicate first row of the expert)
    int total = offp[NUM_EXPERTS];
    for (int s = t; s < total; s += blockDim.x) {
        int ee = 0;
        while (s >= offp[ee + 1]) ee++;
        int local = s - offp[ee];
        int c = cnt[ee];
        int src = (local < c) ? local : (c - 1);   // c>0 guaranteed if tile exists
        g_orderp[s] = g_order[off[ee] + src];
    }
}

// ---------------------------------------------------------------------------
// cp.async helpers
// ---------------------------------------------------------------------------
__device__ __forceinline__ void cp_async16(void* smem_dst, const void* gsrc)
{
    uint32_t s = (uint32_t)__cvta_generic_to_shared(smem_dst);
    asm volatile("cp.async.cg.shared.global [%0], [%1], 16;\n" :: "r"(s), "l"(gsrc));
}
__device__ __forceinline__ void cp_async_commit() { asm volatile("cp.async.commit_group;\n"); }
__device__ __forceinline__ void cp_async_wait_all() { asm volatile("cp.async.wait_group 0;\n"); }

// ---------------------------------------------------------------------------
// grouped GEMM, double buffered. block = (n-tile, work item).
//   BM=64 x BN=32 x BK=16, 128 threads, 4x4 micro-tile.
// ---------------------------------------------------------------------------
__global__ __launch_bounds__(THREADS)
void gemm_kernel(const float* __restrict__ x,
                 const float* __restrict__ ws,
                 const float* __restrict__ bs,
                 float* __restrict__ out)
{
    const int by = blockIdx.y;
    if (by >= g_nwork) return;

    const int e     = g_we[by];
    const int start = g_wstart[by];
    const int valid = g_wvalid[by];
    const int n0    = blockIdx.x * BN;

    __shared__ float As[2][BK][BM + 4];   // row = 68 floats -> conflict-free
    __shared__ float Bs[2][BK][BN];

    const int t   = threadIdx.x;
    const int tx4 = (t & 7) * 4;          // n micro offset (0..28)
    const int ty  = t >> 3;               // m micro group (0..15)

    // A-load mapping: row = t>>1 (0..63); k chunks c and c+8, c=(t&1)*4
    const int a_row = t >> 1;
    const int a_c   = (t & 1) * 4;
    const int grow  = g_orderp[start + a_row];
    const float* xrow = x + (size_t)grow * IDIM + a_c;

    // B-load mapping: one 16B cp.async per thread per tile
    const int b_k  = t >> 3;              // 0..15
    const int b_n4 = (t & 7) * 4;         // 0..28
    const float* wsrc = ws + ((size_t)e * IDIM + b_k) * UNITS + n0 + b_n4;

    float acc[4][4];
#pragma unroll
    for (int i = 0; i < 4; i++)
#pragma unroll
        for (int j = 0; j < 4; j++) acc[i][j] = 0.0f;

    // ---- prologue: tile 0 ----
    cp_async16(&Bs[0][b_k][b_n4], wsrc);
    cp_async_commit();
    float4 a0 = *(const float4*)(xrow);
    float4 a1 = *(const float4*)(xrow + 8);
#pragma unroll
    for (int q = 0; q < 4; q++) {
        As[0][a_c + q][a_row]     = ((const float*)&a0)[q];
        As[0][a_c + 8 + q][a_row] = ((const float*)&a1)[q];
    }
    cp_async_wait_all();
    __syncthreads();

    float4 an0, an1;
    for (int tk = 0; tk < KTILES; tk++) {
        const int cur = tk & 1;
        const int nxt = cur ^ 1;
        const bool has_next = (tk + 1 < KTILES);

        if (has_next) {
            cp_async16(&Bs[nxt][b_k][b_n4], wsrc + (size_t)(tk + 1) * BK * UNITS);
            cp_async_commit();
            an0 = *(const float4*)(xrow + (tk + 1) * BK);
            an1 = *(const float4*)(xrow + (tk + 1) * BK + 8);
        }

#pragma unroll
        for (int k = 0; k < BK; k++) {
            float4 a = *(const float4*)&As[cur][k][ty * 4];
            float4 b = *(const float4*)&Bs[cur][k][tx4];
            acc[0][0] += a.x * b.x; acc[0][1] += a.x * b.y; acc[0][2] += a.x * b.z; acc[0][3] += a.x * b.w;
            acc[1][0] += a.y * b.x; acc[1][1] += a.y * b.y; acc[1][2] += a.y * b.z; acc[1][3] += a.y * b.w;
            acc[2][0] += a.z * b.x; acc[2][1] += a.z * b.y; acc[2][2] += a.z * b.z; acc[2][3] += a.z * b.w;
            acc[3][0] += a.w * b.x; acc[3][1] += a.w * b.y; acc[3][2] += a.w * b.z; acc[3][3] += a.w * b.w;
        }

        if (has_next) {
#pragma unroll
            for (int q = 0; q < 4; q++) {
                As[nxt][a_c + q][a_row]     = ((const float*)&an0)[q];
                As[nxt][a_c + 8 + q][a_row] = ((const float*)&an1)[q];
            }
            cp_async_wait_all();
            __syncthreads();
        }
    }

    // ---- epilogue: bias + relu, masked scatter ----
    float4 bias = *(const float4*)&bs[e * UNITS + n0 + tx4];
#pragma unroll
    for (int i = 0; i < 4; i++) {
        int m = ty * 4 + i;
        if (m < valid) {
            int gr = g_orderp[start + m];
            float4 r;
            r.x = fmaxf(acc[i][0] + bias.x, 0.0f);
            r.y = fmaxf(acc[i][1] + bias.y, 0.0f);
            r.z = fmaxf(acc[i][2] + bias.z, 0.0f);
            r.w = fmaxf(acc[i][3] + bias.w, 0.0f);
            *(float4*)&out[(size_t)gr * UNITS + n0 + tx4] = r;
        }
    }
}

extern "C" void kernel_launch(void* const* d_in, const int* in_sizes, int n_in,
                              void* d_out, int out_size)
{
    const float* x   = (const float*)d_in[0];
    const void*  idx = d_in[1];
    const float* ws  = (const float*)d_in[2];
    const float* bs  = (const float*)d_in[3];
    float* out = (float*)d_out;

    prep_kernel<<<1, BATCH>>>(idx);
    dim3 grid(UNITS / BN, MAX_WORK);
    gemm_kernel<<<grid, THREADS>>>(x, ws, bs, out);
}

// round 4
// speedup vs baseline: 1.7124x; 1.4226x over previous
#include <cuda_runtime.h>
#include <cuda_bf16.h>
#include <cstdint>

#define NUM_EXPERTS 16
#define BATCH       1024
#define IDIM        512
#define UNITS       512

#define BM 64
#define BN 32
#define BK 32
#define THREADS 128
#define KCHUNKS (IDIM / BK)        // 16
#define MAX_WORK 32                // sum ceil(cnt/64) <= 31

// smem per stage (bytes): A hi/lo 64 rows x 80B, B hi/lo 32 rows x 80B
#define A_ROW_B   80
#define A_BUF     (64 * A_ROW_B)   // 5120
#define B_ROW_B   80
#define B_BUF     (32 * B_ROW_B)   // 2560
#define AH_OFF    0
#define AL_OFF    (A_BUF)
#define BH_OFF    (2 * A_BUF)
#define BL_OFF    (2 * A_BUF + B_BUF)
#define STAGE_B   (2 * A_BUF + 2 * B_BUF)   // 15360

// ---------------- device scratch (allocation-free) ----------------
__device__ int g_order[BATCH];
__device__ int g_orderp[MAX_WORK * BM];
__device__ int g_we[MAX_WORK];
__device__ int g_wstart[MAX_WORK];
__device__ int g_wvalid[MAX_WORK];
__device__ int g_nwork;

// ---------------------------------------------------------------------------
// prep: counting sort by expert, padded order, work list (BM=64 tiles).
// Auto-detects int64 vs int32 index buffer.
// ---------------------------------------------------------------------------
__global__ void prep_kernel(const void* idx_raw)
{
    const int* i32 = (const int*)idx_raw;
    __shared__ int cnt[NUM_EXPERTS];
    __shared__ int off[NUM_EXPERTS + 1];
    __shared__ int offp[NUM_EXPERTS + 1];
    __shared__ int cur[NUM_EXPERTS];
    __shared__ int odd_nonzero;

    int t = threadIdx.x;
    if (t == 0) odd_nonzero = 0;
    if (t < NUM_EXPERTS) { cnt[t] = 0; cur[t] = 0; }
    __syncthreads();

    if (t < 512) {
        if (i32[2 * t + 1] != 0) atomicOr(&odd_nonzero, 1);
    }
    __syncthreads();

    int e;
    if (odd_nonzero) e = i32[t];          // int32 data
    else             e = i32[2 * t];      // int64 data, low word
    e &= (NUM_EXPERTS - 1);

    atomicAdd(&cnt[e], 1);
    __syncthreads();

    if (t == 0) {
        int s = 0, sp = 0, nw = 0;
        for (int i = 0; i < NUM_EXPERTS; i++) {
            off[i] = s;
            offp[i] = sp;
            int c = cnt[i];
            int tiles = (c + BM - 1) / BM;
            for (int j = 0; j < tiles; j++) {
                g_we[nw] = i;
                g_wstart[nw] = sp + j * BM;
                int v = c - j * BM;
                g_wvalid[nw] = (v < BM) ? v : BM;
                nw++;
            }
            s += c;
            sp += tiles * BM;
        }
        off[NUM_EXPERTS] = s;
        offp[NUM_EXPERTS] = sp;
        g_nwork = nw;
    }
    __syncthreads();

    int p = atomicAdd(&cur[e], 1);
    g_order[off[e] + p] = t;
    __syncthreads();

    int total = offp[NUM_EXPERTS];
    for (int s = t; s < total; s += blockDim.x) {
        int ee = 0;
        while (s >= offp[ee + 1]) ee++;
        int local = s - offp[ee];
        int c = cnt[ee];
        int src = (local < c) ? local : (c - 1);
        g_orderp[s] = g_order[off[ee] + src];
    }
}

// ---------------- mma / ldmatrix / convert helpers ----------------
__device__ __forceinline__ uint32_t smem_u32(const void* p)
{ return (uint32_t)__cvta_generic_to_shared(p); }

__device__ __forceinline__ void ldsm4(uint32_t addr, uint32_t* r)
{
    asm volatile("ldmatrix.sync.aligned.m8n8.x4.shared.b16 {%0,%1,%2,%3}, [%4];"
                 : "=r"(r[0]), "=r"(r[1]), "=r"(r[2]), "=r"(r[3]) : "r"(addr));
}
__device__ __forceinline__ void ldsm4t(uint32_t addr, uint32_t* r)
{
    asm volatile("ldmatrix.sync.aligned.m8n8.x4.trans.shared.b16 {%0,%1,%2,%3}, [%4];"
                 : "=r"(r[0]), "=r"(r[1]), "=r"(r[2]), "=r"(r[3]) : "r"(addr));
}
__device__ __forceinline__ void mma16816(float* c, const uint32_t* a, const uint32_t* b)
{
    asm volatile("mma.sync.aligned.m16n8k16.row.col.f32.bf16.bf16.f32 "
                 "{%0,%1,%2,%3}, {%4,%5,%6,%7}, {%8,%9}, {%0,%1,%2,%3};"
                 : "+f"(c[0]), "+f"(c[1]), "+f"(c[2]), "+f"(c[3])
                 : "r"(a[0]), "r"(a[1]), "r"(a[2]), "r"(a[3]),
                   "r"(b[0]), "r"(b[1]));
}

// pack two fp32 -> bf16x2 (lo = first arg), and residual pack
__device__ __forceinline__ uint32_t pack_bf16(float lo, float hi)
{
    uint32_t r;
    asm("cvt.rn.bf16x2.f32 %0, %1, %2;" : "=r"(r) : "f"(hi), "f"(lo));
    return r;
}
// 8 fp32 -> hi uint4 + lo-residual uint4 (4 bf16x2 each)
__device__ __forceinline__ void cvt8(const float* f, uint4& H, uint4& L)
{
    uint32_t h[4], l[4];
#pragma unroll
    for (int i = 0; i < 4; i++) {
        float a = f[2 * i], b = f[2 * i + 1];
        uint32_t hp = pack_bf16(a, b);
        float ra = a - __uint_as_float(hp << 16);
        float rb = b - __uint_as_float(hp & 0xFFFF0000u);
        h[i] = hp;
        l[i] = pack_bf16(ra, rb);
    }
    H = make_uint4(h[0], h[1], h[2], h[3]);
    L = make_uint4(l[0], l[1], l[2], l[3]);
}

// ---------------------------------------------------------------------------
// grouped GEMM on tensor cores (mma.sync bf16, 3-term fp32 split).
// block = (n-tile 0..15, work item). BM=64, BN=32, BK=32 chunks, 4 warps.
// ---------------------------------------------------------------------------
__global__ __launch_bounds__(THREADS)
void gemm_kernel(const float* __restrict__ x,
                 const float* __restrict__ ws,
                 const float* __restrict__ bs,
                 float* __restrict__ out)
{
    const int by = blockIdx.y;
    if (by >= g_nwork) return;

    const int e     = g_we[by];
    const int start = g_wstart[by];
    const int valid = g_wvalid[by];
    const int n0    = blockIdx.x * BN;

    __shared__ __align__(16) char smem[2][STAGE_B];
    __shared__ float s_bias[BN];

    const int t    = threadIdx.x;
    const int lane = t & 31;
    const int w    = t >> 5;
    const int wm   = w & 1;      // m warp (0..1) -> rows wm*32..+31
    const int wn   = w >> 1;     // n warp (0..1) -> cols wn*16..+15

    if (t < BN) s_bias[t] = bs[e * UNITS + n0 + t];

    // ---- producer mappings ----
    // A: thread covers row (t>>1), k-halfchunk (t&1)*16 (16 fp32)
    const int a_row = t >> 1;
    const int a_kh  = (t & 1) * 16;
    const int grow  = g_orderp[start + a_row];
    const float* xrow = x + (size_t)grow * IDIM + a_kh;
    const uint32_t a_st = (uint32_t)(a_row * A_ROW_B + (t & 1) * 32);

    // B: thread covers k-row (t>>2), n-octet (t&3)*8 (8 fp32)
    const int b_k  = t >> 2;
    const int b_nq = (t & 3) * 8;
    const float* wrow = ws + ((size_t)e * IDIM + b_k) * UNITS + n0 + b_nq;
    const uint32_t b_st = (uint32_t)(b_k * B_ROW_B + (t & 3) * 16);

    // ---- consumer lane offsets ----
    const uint32_t sbase = smem_u32(&smem[0][0]);
    const uint32_t a_lane = (uint32_t)((lane & 15) * A_ROW_B + ((lane >> 4) & 1) * 16);
    const uint32_t b_lane = (uint32_t)(((lane & 7) + ((lane >> 3) & 1) * 8) * B_ROW_B
                                       + ((lane >> 4) & 1) * 16);

    float acc[2][2][4];
#pragma unroll
    for (int i = 0; i < 2; i++)
#pragma unroll
        for (int j = 0; j < 2; j++)
#pragma unroll
            for (int q = 0; q < 4; q++) acc[i][j][q] = 0.0f;

    // ---- prologue: chunk 0 -> regs -> smem[0] ----
    float4 pa[4], pb[2];
#pragma unroll
    for (int q = 0; q < 4; q++) pa[q] = *(const float4*)(xrow + q * 4);
    pb[0] = *(const float4*)(wrow);
    pb[1] = *(const float4*)(wrow + 4);
    {
        uint4 H0, L0, H1, L1;
        cvt8((const float*)&pa[0], H0, L0);
        cvt8((const float*)&pa[2], H1, L1);
        *(uint4*)(&smem[0][AH_OFF + a_st])      = H0;
        *(uint4*)(&smem[0][AH_OFF + a_st + 16]) = H1;
        *(uint4*)(&smem[0][AL_OFF + a_st])      = L0;
        *(uint4*)(&smem[0][AL_OFF + a_st + 16]) = L1;
        uint4 BH, BL;
        cvt8((const float*)&pb[0], BH, BL);
        *(uint4*)(&smem[0][BH_OFF + b_st]) = BH;
        *(uint4*)(&smem[0][BL_OFF + b_st]) = BL;
    }
    __syncthreads();

    for (int c = 0; c < KCHUNKS; c++) {
        const int s = c & 1;
        const bool has_next = (c + 1 < KCHUNKS);

        if (has_next) {
#pragma unroll
            for (int q = 0; q < 4; q++)
                pa[q] = *(const float4*)(xrow + (c + 1) * BK + q * 4);
            pb[0] = *(const float4*)(wrow + (size_t)(c + 1) * BK * UNITS);
            pb[1] = *(const float4*)(wrow + (size_t)(c + 1) * BK * UNITS + 4);
        }

        // ---- compute chunk c from smem[s] ----
        const uint32_t Ah = sbase + (uint32_t)(s * STAGE_B + AH_OFF);
        const uint32_t Al = sbase + (uint32_t)(s * STAGE_B + AL_OFF);
        const uint32_t Bh = sbase + (uint32_t)(s * STAGE_B + BH_OFF);
        const uint32_t Bl = sbase + (uint32_t)(s * STAGE_B + BL_OFF);

#pragma unroll
        for (int ks = 0; ks < 2; ks++) {
            uint32_t aH[2][4], aL[2][4], bH[4], bL[4];
#pragma unroll
            for (int i = 0; i < 2; i++) {
                uint32_t ao = (uint32_t)(wm * 32 * A_ROW_B + i * 16 * A_ROW_B + ks * 32) + a_lane;
                ldsm4(Ah + ao, aH[i]);
                ldsm4(Al + ao, aL[i]);
            }
            {
                uint32_t bo = (uint32_t)(ks * 16 * B_ROW_B + wn * 32) + b_lane;
                ldsm4t(Bh + bo, bH);
                ldsm4t(Bl + bo, bL);
            }
#pragma unroll
            for (int i = 0; i < 2; i++) {
#pragma unroll
                for (int j = 0; j < 2; j++) {
                    mma16816(acc[i][j], aH[i], &bH[j * 2]);
                    mma16816(acc[i][j], aH[i], &bL[j * 2]);
                    mma16816(acc[i][j], aL[i], &bH[j * 2]);
                }
            }
        }

        if (has_next) {
            const int ns = s ^ 1;
            uint4 H0, L0, H1, L1;
            cvt8((const float*)&pa[0], H0, L0);
            cvt8((const float*)&pa[2], H1, L1);
            *(uint4*)(&smem[ns][AH_OFF + a_st])      = H0;
            *(uint4*)(&smem[ns][AH_OFF + a_st + 16]) = H1;
            *(uint4*)(&smem[ns][AL_OFF + a_st])      = L0;
            *(uint4*)(&smem[ns][AL_OFF + a_st + 16]) = L1;
            uint4 BH, BL;
            cvt8((const float*)&pb[0], BH, BL);
            *(uint4*)(&smem[ns][BH_OFF + b_st]) = BH;
            *(uint4*)(&smem[ns][BL_OFF + b_st]) = BL;
            __syncthreads();
        }
    }

    // ---- epilogue: bias + relu, masked scatter ----
#pragma unroll
    for (int i = 0; i < 2; i++) {
        int r0 = wm * 32 + i * 16 + (lane >> 2);
        int r1 = r0 + 8;
        int gr0 = (r0 < valid) ? g_orderp[start + r0] : -1;
        int gr1 = (r1 < valid) ? g_orderp[start + r1] : -1;
#pragma unroll
        for (int j = 0; j < 2; j++) {
            int col = wn * 16 + j * 8 + (lane & 3) * 2;
            float b0 = s_bias[col], b1 = s_bias[col + 1];
            if (gr0 >= 0) {
                float2 v;
                v.x = fmaxf(acc[i][j][0] + b0, 0.0f);
                v.y = fmaxf(acc[i][j][1] + b1, 0.0f);
                *(float2*)&out[(size_t)gr0 * UNITS + n0 + col] = v;
            }
            if (gr1 >= 0) {
                float2 v;
                v.x = fmaxf(acc[i][j][2] + b0, 0.0f);
                v.y = fmaxf(acc[i][j][3] + b1, 0.0f);
                *(float2*)&out[(size_t)gr1 * UNITS + n0 + col] = v;
            }
        }
    }
}

extern "C" void kernel_launch(void* const* d_in, const int* in_sizes, int n_in,
                              void* d_out, int out_size)
{
    const float* x   = (const float*)d_in[0];
    const void*  idx = d_in[1];
    const float* ws  = (const float*)d_in[2];
    const float* bs  = (const float*)d_in[3];
    float* out = (float*)d_out;

    prep_kernel<<<1, BATCH>>>(idx);
    dim3 grid(UNITS / BN, MAX_WORK);
    gemm_kernel<<<grid, THREADS>>>(x, ws, bs, out);
}